// round 11
// baseline (speedup 1.0000x reference)
#include <cuda_runtime.h>
#include <cuda_bf16.h>
#include <mma.h>
#include <cstdint>

using namespace nvcuda;

// ===========================================================================
// SpanClassifier via WMMA bf16 hi/lo 3-pass GEMMs (fp32 accumulate).
// (tcgen05 unavailable: harness PTX target is bare sm_103.)
//   q=(X Wq+bq)/32 ; k=X Wk+bk ; S=q k^T + gather(q rel^T) ; mask -> -1e18
// fp32 operands split x = hi + lo (bf16); one GEMM accumulates
// hi*hi + hi*lo + lo*hi over a 3x-K mainloop (lo*lo dropped, ~2^-16 rel).
// R10: 128x256 CTA tile, 64x64 warp tile (LDSM:HMMA 0.5), 1 CTA/SM with
//      255 regs for fragment pipelining, 3-stage cp.async, 1 sync/chunk.
// ===========================================================================

namespace cfg {
constexpr int Bn=4, Tn=2048, Dn=1024, Rn=64;
constexpr int NRpad=256, NRreal=129;
constexpr int Mrows=Bn*Tn;                    // 8192
constexpr int BM=128, BN=256, BK=64;
constexpr int NCH=3*(Dn/BK);                  // 48 chunks (3 passes x 16)
constexpr int STAGES=3;
constexpr int LDS_AB=BK+8;                    // 72 bf16 (144B rows)
constexpr int A_BYTES=BM*LDS_AB*2;            // 18432
constexpr int B_BYTES=BN*LDS_AB*2;            // 36864
constexpr int STAGE_BYTES=A_BYTES+B_BYTES;    // 55296
constexpr int LDS_C=BN+4;                     // 260 floats
constexpr int SMEM_BYTES=STAGES*STAGE_BYTES;  // 165888 (> C stage 133120)
}
using namespace cfg;

// ------------------------------- scratch -----------------------------------
__device__ __nv_bfloat16 g_Xhi[Mrows*Dn], g_Xlo[Mrows*Dn];
__device__ __nv_bfloat16 g_Wt_hi[4][Dn*Dn], g_Wt_lo[4][Dn*Dn];   // W^T [n][k]
__device__ __nv_bfloat16 g_relhi[2][NRpad*Dn], g_rello[2][NRpad*Dn];
__device__ __nv_bfloat16 g_qhi[2][Mrows*Dn], g_qlo[2][Mrows*Dn];
__device__ __nv_bfloat16 g_khi[2][Mrows*Dn], g_klo[2][Mrows*Dn];
__device__ float         g_qr2[2][Mrows*NRpad];

// ----------------------------- async helpers -------------------------------
__device__ __forceinline__ uint32_t smem_u32(const void* p){
    uint32_t a;
    asm("{ .reg .u64 t; cvta.to.shared.u64 t, %1; cvt.u32.u64 %0, t; }":"=r"(a):"l"(p));
    return a;
}
#define CP_ASYNC16(d,s) asm volatile("cp.async.cg.shared.global [%0], [%1], 16;"::"r"(d),"l"(s))
#define CP_COMMIT()     asm volatile("cp.async.commit_group;":::"memory")
#define CP_WAIT1()      asm volatile("cp.async.wait_group 1;":::"memory")
#define CP_WAIT0()      asm volatile("cp.async.wait_group 0;":::"memory")

// ---------------------------------------------------------------------------
// Mainloop: C[128,256] = sum over 48 BK=64 chunks of Atile @ Btile^T.
// 3-stage cp.async ring, single __syncthreads per chunk.
// Result staged in smem as float[128][260]; returns pointer.
// ---------------------------------------------------------------------------
__device__ __forceinline__ float* gemm_stage(
    const __nv_bfloat16* __restrict__ Ah, const __nv_bfloat16* __restrict__ Al,
    const __nv_bfloat16* __restrict__ Bh, const __nv_bfloat16* __restrict__ Bl)
{
    extern __shared__ char smem[];
    const uint32_t sm0 = smem_u32(smem);

    const int tid = threadIdx.x;
    const int wid = tid >> 5;
    const int warp_m = wid >> 2;          // 0..1  (64 rows)
    const int warp_n = wid & 3;           // 0..3  (64 cols)

    // cp.async: A = 1024 x 16B segs (4/thread), B = 2048 segs (8/thread).
    auto load_chunk = [&](int c){
        const int s    = c % STAGES;
        const int pass = c >> 4;
        const int kof  = (c & 15) * BK;
        const __nv_bfloat16* A = (pass == 2) ? Al : Ah;
        const __nv_bfloat16* B = (pass == 1) ? Bl : Bh;
        const uint32_t dA = sm0 + s * STAGE_BYTES;
        const uint32_t dB = dA + A_BYTES;
        #pragma unroll
        for (int l = 0; l < 4; l++) {
            const int f   = tid + l * 256;
            const int row = f >> 3;
            const int sg  = f & 7;
            CP_ASYNC16(dA + (uint32_t)row * (LDS_AB*2) + sg * 16,
                       A + (size_t)row * Dn + kof + sg * 8);
        }
        #pragma unroll
        for (int l = 0; l < 8; l++) {
            const int f   = tid + l * 256;
            const int row = f >> 3;
            const int sg  = f & 7;
            CP_ASYNC16(dB + (uint32_t)row * (LDS_AB*2) + sg * 16,
                       B + (size_t)row * Dn + kof + sg * 8);
        }
    };

    wmma::fragment<wmma::accumulator, 16,16,16, float> acc[4][4];
    #pragma unroll
    for (int m = 0; m < 4; m++)
        #pragma unroll
        for (int n = 0; n < 4; n++) wmma::fill_fragment(acc[m][n], 0.0f);

    load_chunk(0); CP_COMMIT();
    load_chunk(1); CP_COMMIT();

    for (int i = 0; i < NCH; i++) {
        CP_WAIT1();          // chunk i resident (i+1 may be pending)
        __syncthreads();     // all warps done with compute(i-1)
        if (i + 2 < NCH) load_chunk(i + 2);
        CP_COMMIT();         // empty tail groups keep counting uniform

        const int s = i % STAGES;
        const __nv_bfloat16* As =
            (const __nv_bfloat16*)(smem + s * STAGE_BYTES) + warp_m * 64 * LDS_AB;
        const __nv_bfloat16* Bs =
            (const __nv_bfloat16*)(smem + s * STAGE_BYTES + A_BYTES) + warp_n * 64 * LDS_AB;
        #pragma unroll
        for (int ks = 0; ks < 4; ks++) {
            wmma::fragment<wmma::matrix_a, 16,16,16, __nv_bfloat16, wmma::row_major> fa[4];
            wmma::fragment<wmma::matrix_b, 16,16,16, __nv_bfloat16, wmma::col_major> fb[4];
            #pragma unroll
            for (int m = 0; m < 4; m++)
                wmma::load_matrix_sync(fa[m], As + m*16*LDS_AB + ks*16, LDS_AB);
            #pragma unroll
            for (int n = 0; n < 4; n++)
                wmma::load_matrix_sync(fb[n], Bs + n*16*LDS_AB + ks*16, LDS_AB);
            #pragma unroll
            for (int m = 0; m < 4; m++)
                #pragma unroll
                for (int n = 0; n < 4; n++)
                    wmma::mma_sync(acc[m][n], fa[m], fb[n], acc[m][n]);
        }
    }

    CP_WAIT0();
    __syncthreads();         // all compute done before C overwrites buffers

    float* Cs = (float*)smem;
    #pragma unroll
    for (int m = 0; m < 4; m++)
        #pragma unroll
        for (int n = 0; n < 4; n++)
            wmma::store_matrix_sync(
                Cs + (warp_m*64 + m*16) * LDS_C + warp_n*64 + n*16,
                acc[m][n], LDS_C, wmma::mem_row_major);
    __syncthreads();
    return Cs;
}

// ------------------------------ conversions --------------------------------
__global__ void convert_X(const float* __restrict__ s) {
    int i = blockIdx.x * 256 + threadIdx.x;              // over float2
    float2 v = reinterpret_cast<const float2*>(s)[i];
    __nv_bfloat16 h0 = __float2bfloat16(v.x), h1 = __float2bfloat16(v.y);
    reinterpret_cast<__nv_bfloat162*>(g_Xhi)[i] = __nv_bfloat162(h0, h1);
    reinterpret_cast<__nv_bfloat162*>(g_Xlo)[i] = __nv_bfloat162(
        __float2bfloat16(v.x - __bfloat162float(h0)),
        __float2bfloat16(v.y - __bfloat162float(h1)));
}

__global__ void convert_Wt(const float* __restrict__ W0, const float* __restrict__ W1,
                           const float* __restrict__ W2, const float* __restrict__ W3) {
    __shared__ float t[32][33];
    const int z = blockIdx.z;
    const float* W = (z==0)?W0:(z==1)?W1:(z==2)?W2:W3;
    const int x0 = blockIdx.x * 32, y0 = blockIdx.y * 32;    // x: n, y: k
    const int tx = threadIdx.x, ty = threadIdx.y;
    #pragma unroll
    for (int i = 0; i < 4; i++)
        t[ty + i*8][tx] = W[(size_t)(y0 + ty + i*8) * Dn + x0 + tx];
    __syncthreads();
    #pragma unroll
    for (int i = 0; i < 4; i++) {
        float v = t[tx][ty + i*8];
        __nv_bfloat16 h = __float2bfloat16(v);
        size_t o = (size_t)(x0 + ty + i*8) * Dn + y0 + tx;
        g_Wt_hi[z][o] = h;
        g_Wt_lo[z][o] = __float2bfloat16(v - __bfloat162float(h));
    }
}

__global__ void convert_rel(const float* __restrict__ r0, const float* __restrict__ r1) {
    const int h = blockIdx.y, row = blockIdx.x;
    const float* src = h ? r1 : r0;
    __nv_bfloat16* oh = g_relhi[h] + (size_t)row * Dn;
    __nv_bfloat16* ol = g_rello[h] + (size_t)row * Dn;
    for (int c = threadIdx.x; c < Dn; c += 256) {
        float v = (row < NRreal) ? src[(size_t)row * Dn + c] : 0.f;
        __nv_bfloat16 hh = __float2bfloat16(v);
        oh[c] = hh;
        ol[c] = __float2bfloat16(v - __bfloat162float(hh));
    }
}

// ------------------------------- GEMM kernels ------------------------------
__global__ __launch_bounds__(256, 1)
void proj_mma(const float* __restrict__ bq0, const float* __restrict__ bk0,
              const float* __restrict__ bq1, const float* __restrict__ bk1) {
    const int z = blockIdx.z;
    const int rowBase = blockIdx.y * BM, colBase = blockIdx.x * BN;
    float* Cs = gemm_stage(g_Xhi + (size_t)rowBase * Dn, g_Xlo + (size_t)rowBase * Dn,
                           g_Wt_hi[z] + (size_t)colBase * Dn,
                           g_Wt_lo[z] + (size_t)colBase * Dn);
    const float* bias = (z==0)?bq0:(z==1)?bk0:(z==2)?bq1:bk1;
    const float alpha = (z & 1) ? 1.0f : 0.03125f;     // q gets 1/sqrt(1024)
    __nv_bfloat16* oh = (z==0)?g_qhi[0]:(z==1)?g_khi[0]:(z==2)?g_qhi[1]:g_khi[1];
    __nv_bfloat16* ol = (z==0)?g_qlo[0]:(z==1)?g_klo[0]:(z==2)?g_qlo[1]:g_klo[1];
    for (int it = threadIdx.x; it < BM * BN; it += 256) {
        const int row = it >> 8, c = it & 255;
        float v = (Cs[row * LDS_C + c] + bias[colBase + c]) * alpha;
        __nv_bfloat16 h = __float2bfloat16(v);
        size_t o = (size_t)(rowBase + row) * Dn + colBase + c;
        oh[o] = h;
        ol[o] = __float2bfloat16(v - __bfloat162float(h));
    }
}

__global__ __launch_bounds__(256, 1)
void qr_mma() {
    const int h = blockIdx.z;
    const int rowBase = blockIdx.y * BM;
    float* Cs = gemm_stage(g_qhi[h] + (size_t)rowBase * Dn,
                           g_qlo[h] + (size_t)rowBase * Dn,
                           g_relhi[h], g_rello[h]);
    for (int it = threadIdx.x; it < BM * BN; it += 256) {
        const int row = it >> 8, c = it & 255;
        g_qr2[h][(size_t)(rowBase + row) * NRpad + c] = Cs[row * LDS_C + c];
    }
}

__global__ __launch_bounds__(256, 1)
void scores_mma(const int* __restrict__ mask, float* __restrict__ gout) {
    const int z = blockIdx.z, h = z >> 2, b = z & 3;
    const int rowBase = blockIdx.y * BM, colBase = blockIdx.x * BN;
    float* Cs = gemm_stage(g_qhi[h] + ((size_t)b * Tn + rowBase) * Dn,
                           g_qlo[h] + ((size_t)b * Tn + rowBase) * Dn,
                           g_khi[h] + ((size_t)b * Tn + colBase) * Dn,
                           g_klo[h] + ((size_t)b * Tn + colBase) * Dn);
    const float* QR  = g_qr2[h] + (size_t)b * Tn * NRpad;
    const int*   Msk = mask + (size_t)b * Tn * Tn;
    float*       Out = gout + (size_t)h * Bn * Tn * Tn + (size_t)b * Tn * Tn;
    for (int it = threadIdx.x; it < BM * BN; it += 256) {
        const int row = it >> 8, c = it & 255;
        const int i = rowBase + row, j = colBase + c;
        int d = j - i; d = d < -Rn ? -Rn : (d > Rn ? Rn : d);
        float v = Cs[row * LDS_C + c] + QR[(size_t)i * NRpad + d + Rn];
        Out[(size_t)i * Tn + j] = Msk[(size_t)i * Tn + j] ? v : -1e18f;
    }
}

// --------------------------------- launch ----------------------------------
extern "C" void kernel_launch(void* const* d_in, const int* in_sizes, int n_in,
                              void* d_out, int out_size)
{
    (void)in_sizes; (void)n_in; (void)out_size;
    const float* repre  = (const float*)d_in[0];
    const int*   mask   = (const int*)  d_in[1];
    const float* st_Wq  = (const float*)d_in[2];
    const float* st_bq  = (const float*)d_in[3];
    const float* st_Wk  = (const float*)d_in[4];
    const float* st_bk  = (const float*)d_in[5];
    const float* st_rel = (const float*)d_in[6];
    const float* ed_Wq  = (const float*)d_in[7];
    const float* ed_bq  = (const float*)d_in[8];
    const float* ed_Wk  = (const float*)d_in[9];
    const float* ed_bk  = (const float*)d_in[10];
    const float* ed_rel = (const float*)d_in[11];
    float* out = (float*)d_out;

    static bool attr_set = false;
    if (!attr_set) {
        cudaFuncSetAttribute(proj_mma,   cudaFuncAttributeMaxDynamicSharedMemorySize, SMEM_BYTES);
        cudaFuncSetAttribute(qr_mma,     cudaFuncAttributeMaxDynamicSharedMemorySize, SMEM_BYTES);
        cudaFuncSetAttribute(scores_mma, cudaFuncAttributeMaxDynamicSharedMemorySize, SMEM_BYTES);
        attr_set = true;
    }

    convert_X  <<<Mrows * Dn / 512, 256>>>(repre);
    convert_Wt <<<dim3(32, 32, 4), dim3(32, 8)>>>(st_Wq, st_Wk, ed_Wq, ed_Wk);
    convert_rel<<<dim3(NRpad, 2), 256>>>(st_rel, ed_rel);

    proj_mma  <<<dim3(Dn/BN, Mrows/BM, 4), 256, SMEM_BYTES>>>(st_bq, st_bk, ed_bq, ed_bk);
    qr_mma    <<<dim3(1, Mrows/BM, 2),     256, SMEM_BYTES>>>();
    scores_mma<<<dim3(Tn/BN, Tn/BM, 8),    256, SMEM_BYTES>>>(mask, out);
}

// round 12
// speedup vs baseline: 1.1348x; 1.1348x over previous
#include <cuda_runtime.h>
#include <cuda_bf16.h>
#include <mma.h>
#include <cstdint>

using namespace nvcuda;

// ===========================================================================
// SpanClassifier via WMMA bf16 hi/lo 3-pass GEMMs (fp32 accumulate).
// (tcgen05 unavailable: harness PTX target is bare sm_103.)
//   q=(X Wq+bq)/32 ; k=X Wk+bk ; S=q k^T + gather(q rel^T) ; mask -> -1e18
// fp32 operands split x = hi + lo (bf16); one GEMM accumulates
// hi*hi + hi*lo + lo*hi over a 3x-K mainloop (lo*lo dropped, ~2^-16 rel).
// R12: 128-thread CTAs (4 warps), 128x128 CTA tile, 64x64 warp tile,
//      2 CTAs/SM (reg budget 252x128x2 < 64K), 3-stage cp.async ring,
//      one __syncthreads per BK=64 chunk.
// ===========================================================================

namespace cfg {
constexpr int Bn=4, Tn=2048, Dn=1024, Rn=64;
constexpr int NRpad=256, NRreal=129;
constexpr int Mrows=Bn*Tn;                    // 8192
constexpr int BM=128, BN=128, BK=64;
constexpr int NTH=128;
constexpr int NCH=3*(Dn/BK);                  // 48 chunks (3 passes x 16)
constexpr int STAGES=3;
constexpr int LDS_AB=BK+8;                    // 72 bf16 (144B rows)
constexpr int AB_BYTES=BM*LDS_AB*2;           // 18432 per matrix tile
constexpr int STAGE_BYTES=2*AB_BYTES;         // 36864
constexpr int LDS_C=BN+4;                     // 132 floats
constexpr int SMEM_BYTES=STAGES*STAGE_BYTES;  // 110592 (> C stage 67584)
}
using namespace cfg;

// ------------------------------- scratch -----------------------------------
__device__ __nv_bfloat16 g_Xhi[Mrows*Dn], g_Xlo[Mrows*Dn];
__device__ __nv_bfloat16 g_Wt_hi[4][Dn*Dn], g_Wt_lo[4][Dn*Dn];   // W^T [n][k]
__device__ __nv_bfloat16 g_relhi[2][NRpad*Dn], g_rello[2][NRpad*Dn];
__device__ __nv_bfloat16 g_qhi[2][Mrows*Dn], g_qlo[2][Mrows*Dn];
__device__ __nv_bfloat16 g_khi[2][Mrows*Dn], g_klo[2][Mrows*Dn];
__device__ float         g_qr2[2][Mrows*NRpad];

// ----------------------------- async helpers -------------------------------
__device__ __forceinline__ uint32_t smem_u32(const void* p){
    uint32_t a;
    asm("{ .reg .u64 t; cvta.to.shared.u64 t, %1; cvt.u32.u64 %0, t; }":"=r"(a):"l"(p));
    return a;
}
#define CP_ASYNC16(d,s) asm volatile("cp.async.cg.shared.global [%0], [%1], 16;"::"r"(d),"l"(s))
#define CP_COMMIT()     asm volatile("cp.async.commit_group;":::"memory")
#define CP_WAIT1()      asm volatile("cp.async.wait_group 1;":::"memory")
#define CP_WAIT0()      asm volatile("cp.async.wait_group 0;":::"memory")

// ---------------------------------------------------------------------------
// Mainloop: C[128,128] = sum over 48 BK=64 chunks of Atile @ Btile^T.
// 4 warps, warp tile 64x64. 3-stage cp.async ring, one sync per chunk.
// Result staged in smem as float[128][132]; returns pointer.
// ---------------------------------------------------------------------------
__device__ __forceinline__ float* gemm_stage(
    const __nv_bfloat16* __restrict__ Ah, const __nv_bfloat16* __restrict__ Al,
    const __nv_bfloat16* __restrict__ Bh, const __nv_bfloat16* __restrict__ Bl)
{
    extern __shared__ char smem[];
    const uint32_t sm0 = smem_u32(smem);

    const int tid = threadIdx.x;
    const int wid = tid >> 5;
    const int warp_m = wid >> 1;          // 0..1  (64 rows)
    const int warp_n = wid & 1;           // 0..1  (64 cols)

    // cp.async: per matrix 128 rows x 8 x 16B segs = 1024; 8 per thread.
    auto load_chunk = [&](int c){
        const int s    = c % STAGES;
        const int pass = c >> 4;
        const int kof  = (c & 15) * BK;
        const __nv_bfloat16* A = (pass == 2) ? Al : Ah;
        const __nv_bfloat16* B = (pass == 1) ? Bl : Bh;
        const uint32_t dA = sm0 + s * STAGE_BYTES;
        const uint32_t dB = dA + AB_BYTES;
        #pragma unroll
        for (int l = 0; l < 8; l++) {
            const int f   = tid + l * NTH;
            const int row = f >> 3;
            const int sg  = f & 7;
            const uint32_t so = (uint32_t)row * (LDS_AB*2) + sg * 16;
            const size_t   go = (size_t)row * Dn + kof + sg * 8;
            CP_ASYNC16(dA + so, A + go);
            CP_ASYNC16(dB + so, B + go);
        }
    };

    wmma::fragment<wmma::accumulator, 16,16,16, float> acc[4][4];
    #pragma unroll
    for (int m = 0; m < 4; m++)
        #pragma unroll
        for (int n = 0; n < 4; n++) wmma::fill_fragment(acc[m][n], 0.0f);

    load_chunk(0); CP_COMMIT();
    load_chunk(1); CP_COMMIT();

    for (int i = 0; i < NCH; i++) {
        CP_WAIT1();          // chunk i resident (i+1 may be pending)
        __syncthreads();     // all warps done with compute(i-1)
        if (i + 2 < NCH) load_chunk(i + 2);
        CP_COMMIT();         // empty tail groups keep counting uniform

        const int s = i % STAGES;
        const __nv_bfloat16* As =
            (const __nv_bfloat16*)(smem + s * STAGE_BYTES) + warp_m * 64 * LDS_AB;
        const __nv_bfloat16* Bs =
            (const __nv_bfloat16*)(smem + s * STAGE_BYTES + AB_BYTES) + warp_n * 64 * LDS_AB;
        #pragma unroll
        for (int ks = 0; ks < 4; ks++) {
            wmma::fragment<wmma::matrix_a, 16,16,16, __nv_bfloat16, wmma::row_major> fa[4];
            wmma::fragment<wmma::matrix_b, 16,16,16, __nv_bfloat16, wmma::col_major> fb[4];
            #pragma unroll
            for (int m = 0; m < 4; m++)
                wmma::load_matrix_sync(fa[m], As + m*16*LDS_AB + ks*16, LDS_AB);
            #pragma unroll
            for (int n = 0; n < 4; n++)
                wmma::load_matrix_sync(fb[n], Bs + n*16*LDS_AB + ks*16, LDS_AB);
            #pragma unroll
            for (int m = 0; m < 4; m++)
                #pragma unroll
                for (int n = 0; n < 4; n++)
                    wmma::mma_sync(acc[m][n], fa[m], fb[n], acc[m][n]);
        }
    }

    CP_WAIT0();
    __syncthreads();         // all compute done before C overwrites buffers

    float* Cs = (float*)smem;
    #pragma unroll
    for (int m = 0; m < 4; m++)
        #pragma unroll
        for (int n = 0; n < 4; n++)
            wmma::store_matrix_sync(
                Cs + (warp_m*64 + m*16) * LDS_C + warp_n*64 + n*16,
                acc[m][n], LDS_C, wmma::mem_row_major);
    __syncthreads();
    return Cs;
}

// ------------------------------ conversions --------------------------------
__global__ void convert_X(const float* __restrict__ s) {
    int i = blockIdx.x * 256 + threadIdx.x;              // over float2
    float2 v = reinterpret_cast<const float2*>(s)[i];
    __nv_bfloat16 h0 = __float2bfloat16(v.x), h1 = __float2bfloat16(v.y);
    reinterpret_cast<__nv_bfloat162*>(g_Xhi)[i] = __nv_bfloat162(h0, h1);
    reinterpret_cast<__nv_bfloat162*>(g_Xlo)[i] = __nv_bfloat162(
        __float2bfloat16(v.x - __bfloat162float(h0)),
        __float2bfloat16(v.y - __bfloat162float(h1)));
}

__global__ void convert_Wt(const float* __restrict__ W0, const float* __restrict__ W1,
                           const float* __restrict__ W2, const float* __restrict__ W3) {
    __shared__ float t[32][33];
    const int z = blockIdx.z;
    const float* W = (z==0)?W0:(z==1)?W1:(z==2)?W2:W3;
    const int x0 = blockIdx.x * 32, y0 = blockIdx.y * 32;    // x: n, y: k
    const int tx = threadIdx.x, ty = threadIdx.y;
    #pragma unroll
    for (int i = 0; i < 4; i++)
        t[ty + i*8][tx] = W[(size_t)(y0 + ty + i*8) * Dn + x0 + tx];
    __syncthreads();
    #pragma unroll
    for (int i = 0; i < 4; i++) {
        float v = t[tx][ty + i*8];
        __nv_bfloat16 h = __float2bfloat16(v);
        size_t o = (size_t)(x0 + ty + i*8) * Dn + y0 + tx;
        g_Wt_hi[z][o] = h;
        g_Wt_lo[z][o] = __float2bfloat16(v - __bfloat162float(h));
    }
}

__global__ void convert_rel(const float* __restrict__ r0, const float* __restrict__ r1) {
    const int h = blockIdx.y, row = blockIdx.x;
    const float* src = h ? r1 : r0;
    __nv_bfloat16* oh = g_relhi[h] + (size_t)row * Dn;
    __nv_bfloat16* ol = g_rello[h] + (size_t)row * Dn;
    for (int c = threadIdx.x; c < Dn; c += 256) {
        float v = (row < NRreal) ? src[(size_t)row * Dn + c] : 0.f;
        __nv_bfloat16 hh = __float2bfloat16(v);
        oh[c] = hh;
        ol[c] = __float2bfloat16(v - __bfloat162float(hh));
    }
}

// ------------------------------- GEMM kernels ------------------------------
__global__ __launch_bounds__(NTH, 2)
void proj_mma(const float* __restrict__ bq0, const float* __restrict__ bk0,
              const float* __restrict__ bq1, const float* __restrict__ bk1) {
    const int z = blockIdx.z;
    const int rowBase = blockIdx.y * BM, colBase = blockIdx.x * BN;
    float* Cs = gemm_stage(g_Xhi + (size_t)rowBase * Dn, g_Xlo + (size_t)rowBase * Dn,
                           g_Wt_hi[z] + (size_t)colBase * Dn,
                           g_Wt_lo[z] + (size_t)colBase * Dn);
    const float* bias = (z==0)?bq0:(z==1)?bk0:(z==2)?bq1:bk1;
    const float alpha = (z & 1) ? 1.0f : 0.03125f;     // q gets 1/sqrt(1024)
    __nv_bfloat16* oh = (z==0)?g_qhi[0]:(z==1)?g_khi[0]:(z==2)?g_qhi[1]:g_khi[1];
    __nv_bfloat16* ol = (z==0)?g_qlo[0]:(z==1)?g_klo[0]:(z==2)?g_qlo[1]:g_klo[1];
    for (int it = threadIdx.x; it < BM * BN; it += NTH) {
        const int row = it >> 7, c = it & 127;
        float v = (Cs[row * LDS_C + c] + bias[colBase + c]) * alpha;
        __nv_bfloat16 h = __float2bfloat16(v);
        size_t o = (size_t)(rowBase + row) * Dn + colBase + c;
        oh[o] = h;
        ol[o] = __float2bfloat16(v - __bfloat162float(h));
    }
}

__global__ __launch_bounds__(NTH, 2)
void qr_mma() {
    const int h = blockIdx.z;
    const int rowBase = blockIdx.y * BM, colBase = blockIdx.x * BN;
    float* Cs = gemm_stage(g_qhi[h] + (size_t)rowBase * Dn,
                           g_qlo[h] + (size_t)rowBase * Dn,
                           g_relhi[h] + (size_t)colBase * Dn,
                           g_rello[h] + (size_t)colBase * Dn);
    for (int it = threadIdx.x; it < BM * BN; it += NTH) {
        const int row = it >> 7, c = it & 127;
        g_qr2[h][(size_t)(rowBase + row) * NRpad + colBase + c] = Cs[row * LDS_C + c];
    }
}

__global__ __launch_bounds__(NTH, 2)
void scores_mma(const int* __restrict__ mask, float* __restrict__ gout) {
    const int z = blockIdx.z, h = z >> 2, b = z & 3;
    const int rowBase = blockIdx.y * BM, colBase = blockIdx.x * BN;
    float* Cs = gemm_stage(g_qhi[h] + ((size_t)b * Tn + rowBase) * Dn,
                           g_qlo[h] + ((size_t)b * Tn + rowBase) * Dn,
                           g_khi[h] + ((size_t)b * Tn + colBase) * Dn,
                           g_klo[h] + ((size_t)b * Tn + colBase) * Dn);
    const float* QR  = g_qr2[h] + (size_t)b * Tn * NRpad;
    const int*   Msk = mask + (size_t)b * Tn * Tn;
    float*       Out = gout + (size_t)h * Bn * Tn * Tn + (size_t)b * Tn * Tn;
    for (int it = threadIdx.x; it < BM * BN; it += NTH) {
        const int row = it >> 7, c = it & 127;
        const int i = rowBase + row, j = colBase + c;
        int d = j - i; d = d < -Rn ? -Rn : (d > Rn ? Rn : d);
        float v = Cs[row * LDS_C + c] + QR[(size_t)i * NRpad + d + Rn];
        Out[(size_t)i * Tn + j] = Msk[(size_t)i * Tn + j] ? v : -1e18f;
    }
}

// --------------------------------- launch ----------------------------------
extern "C" void kernel_launch(void* const* d_in, const int* in_sizes, int n_in,
                              void* d_out, int out_size)
{
    (void)in_sizes; (void)n_in; (void)out_size;
    const float* repre  = (const float*)d_in[0];
    const int*   mask   = (const int*)  d_in[1];
    const float* st_Wq  = (const float*)d_in[2];
    const float* st_bq  = (const float*)d_in[3];
    const float* st_Wk  = (const float*)d_in[4];
    const float* st_bk  = (const float*)d_in[5];
    const float* st_rel = (const float*)d_in[6];
    const float* ed_Wq  = (const float*)d_in[7];
    const float* ed_bq  = (const float*)d_in[8];
    const float* ed_Wk  = (const float*)d_in[9];
    const float* ed_bk  = (const float*)d_in[10];
    const float* ed_rel = (const float*)d_in[11];
    float* out = (float*)d_out;

    static bool attr_set = false;
    if (!attr_set) {
        cudaFuncSetAttribute(proj_mma,   cudaFuncAttributeMaxDynamicSharedMemorySize, SMEM_BYTES);
        cudaFuncSetAttribute(qr_mma,     cudaFuncAttributeMaxDynamicSharedMemorySize, SMEM_BYTES);
        cudaFuncSetAttribute(scores_mma, cudaFuncAttributeMaxDynamicSharedMemorySize, SMEM_BYTES);
        attr_set = true;
    }

    convert_X  <<<Mrows * Dn / 512, 256>>>(repre);
    convert_Wt <<<dim3(32, 32, 4), dim3(32, 8)>>>(st_Wq, st_Wk, ed_Wq, ed_Wk);
    convert_rel<<<dim3(NRpad, 2), 256>>>(st_rel, ed_rel);

    proj_mma  <<<dim3(Dn/BN, Mrows/BM, 4), NTH, SMEM_BYTES>>>(st_bq, st_bk, ed_bq, ed_bk);
    qr_mma    <<<dim3(NRpad/BN, Mrows/BM, 2), NTH, SMEM_BYTES>>>();
    scores_mma<<<dim3(Tn/BN, Tn/BM, 8),    NTH, SMEM_BYTES>>>(mask, out);
}

// round 15
// speedup vs baseline: 1.2869x; 1.1340x over previous
#include <cuda_runtime.h>
#include <cuda_bf16.h>
#include <cstdint>

// ===========================================================================
// SpanClassifier via raw mma.sync bf16 hi/lo 3-pass GEMMs (fp32 accumulate).
// (tcgen05 unavailable: harness PTX target is bare sm_103.)
//   q=(X Wq+bq)/32 ; k=X Wk+bk ; S=q k^T + gather(q rel^T) ; mask -> -1e18
// fp32 operands split x = hi + lo (bf16); one GEMM accumulates
// hi*hi + hi*lo + lo*hi over a 3x-K mainloop (lo*lo dropped, ~2^-16 rel).
// R14: R13 with the B-operand fix: smem B is [n][k] (k contiguous) which is
//      already col-major for mma row.col -> NON-trans ldmatrix for B.
//      (.trans delivered B(n,k) swapped -> rel_err 1.41.)
// ===========================================================================

namespace cfg {
constexpr int Bn=4, Tn=2048, Dn=1024, Rn=64;
constexpr int NRpad=256, NRreal=129;
constexpr int Mrows=Bn*Tn;                    // 8192
constexpr int BM=128, BN=128, BK=64;
constexpr int NTH=128;
constexpr int NCH=3*(Dn/BK);                  // 48 chunks (3 passes x 16)
constexpr int STAGES=3;
constexpr int A_BYTES=BM*BK*2;                // 16384 (128B rows, swizzled)
constexpr int STAGE_BYTES=2*A_BYTES;          // 32768
constexpr int LDS_C=BN+4;                     // 132 floats
constexpr int SMEM_BYTES=STAGES*STAGE_BYTES+1024; // 99328 (C stage 67584 fits)
}
using namespace cfg;

// ------------------------------- scratch -----------------------------------
__device__ __nv_bfloat16 g_Xhi[Mrows*Dn], g_Xlo[Mrows*Dn];
__device__ __nv_bfloat16 g_Wt_hi[4][Dn*Dn], g_Wt_lo[4][Dn*Dn];   // W^T [n][k]
__device__ __nv_bfloat16 g_relhi[2][NRpad*Dn], g_rello[2][NRpad*Dn];
__device__ __nv_bfloat16 g_qhi[2][Mrows*Dn], g_qlo[2][Mrows*Dn];
__device__ __nv_bfloat16 g_khi[2][Mrows*Dn], g_klo[2][Mrows*Dn];
__device__ float         g_qr2[2][Mrows*NRpad];

// ----------------------------- PTX helpers ---------------------------------
__device__ __forceinline__ uint32_t smem_u32(const void* p){
    uint32_t a;
    asm("{ .reg .u64 t; cvta.to.shared.u64 t, %1; cvt.u32.u64 %0, t; }":"=r"(a):"l"(p));
    return a;
}
#define CP_ASYNC16(d,s) asm volatile("cp.async.cg.shared.global [%0], [%1], 16;"::"r"(d),"l"(s))
#define CP_COMMIT()     asm volatile("cp.async.commit_group;":::"memory")
#define CP_WAIT1()      asm volatile("cp.async.wait_group 1;":::"memory")
#define CP_WAIT0()      asm volatile("cp.async.wait_group 0;":::"memory")

#define LDSM_X4(r0,r1,r2,r3,a) \
    asm volatile("ldmatrix.sync.aligned.m8n8.x4.shared.b16 {%0,%1,%2,%3}, [%4];" \
                 : "=r"(r0),"=r"(r1),"=r"(r2),"=r"(r3) : "r"(a))
#define MMA16816(d,a,b0,b1) \
    asm volatile("mma.sync.aligned.m16n8k16.row.col.f32.bf16.bf16.f32 " \
                 "{%0,%1,%2,%3}, {%4,%5,%6,%7}, {%8,%9}, {%0,%1,%2,%3};" \
                 : "+f"((d)[0]),"+f"((d)[1]),"+f"((d)[2]),"+f"((d)[3]) \
                 : "r"((a)[0]),"r"((a)[1]),"r"((a)[2]),"r"((a)[3]), "r"(b0),"r"(b1))

// ---------------------------------------------------------------------------
// Mainloop: C[128,128] = sum over 48 BK=64 chunks of Atile @ Btile^T.
// Swizzle: 128B rows; 16B segment s of row r lives at (s ^ (r&7))*16.
// Result staged in smem as float[128][132]; returns pointer.
// ---------------------------------------------------------------------------
__device__ __forceinline__ float* gemm_stage(
    const __nv_bfloat16* __restrict__ Ah, const __nv_bfloat16* __restrict__ Al,
    const __nv_bfloat16* __restrict__ Bh, const __nv_bfloat16* __restrict__ Bl)
{
    extern __shared__ char smem_raw[];
    const uint32_t sm0 = (smem_u32(smem_raw) + 1023) & ~1023u;
    float* Cs = reinterpret_cast<float*>(smem_raw + (sm0 - smem_u32(smem_raw)));

    const int tid = threadIdx.x;
    const int wid = tid >> 5, lane = tid & 31;
    const int warp_m = wid >> 1, warp_n = wid & 1;    // 2x2 warps, 64x64 tiles
    const int lrow = lane & 15, lhalf = lane >> 4;

    // Per-lane ldmatrix address parts (bits [4:7) carry the XOR swizzle).
    uint32_t rpA[4], rpB[4];
    #pragma unroll
    for (int t = 0; t < 4; t++) {
        const int ra = warp_m*64 + t*16 + lrow;
        const int rb = warp_n*64 + t*16 + lrow;
        rpA[t] = (uint32_t)ra*128 + (uint32_t)((lhalf ^ (ra & 7)) << 4);
        rpB[t] = (uint32_t)rb*128 + (uint32_t)((lhalf ^ (rb & 7)) << 4);
    }

    auto load_chunk = [&](int c){
        const int s    = c % STAGES;
        const int pass = c >> 4;
        const int kof  = (c & 15) * BK;
        const __nv_bfloat16* A = (pass == 2) ? Al : Ah;
        const __nv_bfloat16* B = (pass == 1) ? Bl : Bh;
        const uint32_t dA = sm0 + s * STAGE_BYTES;
        const uint32_t dB = dA + A_BYTES;
        #pragma unroll
        for (int l = 0; l < 8; l++) {
            const int f   = tid + l * NTH;
            const int row = f >> 3;
            const int sg  = f & 7;
            const uint32_t so = (uint32_t)row*128 + (uint32_t)((sg ^ (row & 7)) << 4);
            const size_t   go = (size_t)row * Dn + kof + sg * 8;
            CP_ASYNC16(dA + so, A + go);
            CP_ASYNC16(dB + so, B + go);
        }
    };

    float acc[4][8][4];
    #pragma unroll
    for (int m = 0; m < 4; m++)
        #pragma unroll
        for (int n = 0; n < 8; n++)
            #pragma unroll
            for (int e = 0; e < 4; e++) acc[m][n][e] = 0.f;

    load_chunk(0); CP_COMMIT();
    load_chunk(1); CP_COMMIT();

    uint32_t fa[2][4][4], fb[2][4][4];

    for (int i = 0; i < NCH; i++) {
        CP_WAIT1();          // chunk i resident (i+1 may be pending)
        __syncthreads();     // all warps done with compute(i-1)
        if (i + 2 < NCH) load_chunk(i + 2);
        CP_COMMIT();         // empty tail groups keep counting uniform

        const uint32_t dA = sm0 + (i % STAGES) * STAGE_BYTES;
        const uint32_t dB = dA + A_BYTES;

        // Fetch ks=0 fragments (B via NON-trans ldmatrix: smem [n][k] is
        // already col-major for mma row.col).
        #pragma unroll
        for (int t = 0; t < 4; t++) {
            LDSM_X4(fa[0][t][0],fa[0][t][1],fa[0][t][2],fa[0][t][3], dA + rpA[t]);
            LDSM_X4(fb[0][t][0],fb[0][t][1],fb[0][t][2],fb[0][t][3], dB + rpB[t]);
        }
        #pragma unroll
        for (int ks = 0; ks < 4; ks++) {
            const int cur = ks & 1, nxt = cur ^ 1;
            if (ks < 3) {
                const uint32_t x = (uint32_t)((ks + 1) << 5);
                #pragma unroll
                for (int t = 0; t < 4; t++) {
                    LDSM_X4(fa[nxt][t][0],fa[nxt][t][1],fa[nxt][t][2],fa[nxt][t][3],
                            dA + (rpA[t] ^ x));
                    LDSM_X4(fb[nxt][t][0],fb[nxt][t][1],fb[nxt][t][2],fb[nxt][t][3],
                            dB + (rpB[t] ^ x));
                }
            }
            // B x4 regs: r0 = n[0:8)k[0:8), r1 = n[8:16)k[0:8),
            //            r2 = n[0:8)k[8:16), r3 = n[8:16)k[8:16).
            #pragma unroll
            for (int mt = 0; mt < 4; mt++)
                #pragma unroll
                for (int nt = 0; nt < 4; nt++) {
                    MMA16816(acc[mt][nt*2+0], fa[cur][mt], fb[cur][nt][0], fb[cur][nt][2]);
                    MMA16816(acc[mt][nt*2+1], fa[cur][mt], fb[cur][nt][1], fb[cur][nt][3]);
                }
        }
    }

    CP_WAIT0();
    __syncthreads();         // all compute done before C overwrites buffers

    // acc -> Cs. d0,d1: row=lane>>2, col=2*(lane&3)+{0,1}; d2,d3: row+8.
    const int er = lane >> 2, ec = (lane & 3) * 2;
    #pragma unroll
    for (int mt = 0; mt < 4; mt++) {
        const int row0 = warp_m*64 + mt*16 + er;
        #pragma unroll
        for (int j = 0; j < 8; j++) {
            const int col0 = warp_n*64 + (j >> 1)*16 + (j & 1)*8 + ec;
            *reinterpret_cast<float2*>(&Cs[row0*LDS_C + col0]) =
                make_float2(acc[mt][j][0], acc[mt][j][1]);
            *reinterpret_cast<float2*>(&Cs[(row0+8)*LDS_C + col0]) =
                make_float2(acc[mt][j][2], acc[mt][j][3]);
        }
    }
    __syncthreads();
    return Cs;
}

// ------------------------------ conversions --------------------------------
__global__ void convert_X(const float* __restrict__ s) {
    int i = blockIdx.x * 256 + threadIdx.x;              // over float2
    float2 v = reinterpret_cast<const float2*>(s)[i];
    __nv_bfloat16 h0 = __float2bfloat16(v.x), h1 = __float2bfloat16(v.y);
    reinterpret_cast<__nv_bfloat162*>(g_Xhi)[i] = __nv_bfloat162(h0, h1);
    reinterpret_cast<__nv_bfloat162*>(g_Xlo)[i] = __nv_bfloat162(
        __float2bfloat16(v.x - __bfloat162float(h0)),
        __float2bfloat16(v.y - __bfloat162float(h1)));
}

__global__ void convert_Wt(const float* __restrict__ W0, const float* __restrict__ W1,
                           const float* __restrict__ W2, const float* __restrict__ W3) {
    __shared__ float t[32][33];
    const int z = blockIdx.z;
    const float* W = (z==0)?W0:(z==1)?W1:(z==2)?W2:W3;
    const int x0 = blockIdx.x * 32, y0 = blockIdx.y * 32;    // x: n, y: k
    const int tx = threadIdx.x, ty = threadIdx.y;
    #pragma unroll
    for (int i = 0; i < 4; i++)
        t[ty + i*8][tx] = W[(size_t)(y0 + ty + i*8) * Dn + x0 + tx];
    __syncthreads();
    #pragma unroll
    for (int i = 0; i < 4; i++) {
        float v = t[tx][ty + i*8];
        __nv_bfloat16 h = __float2bfloat16(v);
        size_t o = (size_t)(x0 + ty + i*8) * Dn + y0 + tx;
        g_Wt_hi[z][o] = h;
        g_Wt_lo[z][o] = __float2bfloat16(v - __bfloat162float(h));
    }
}

__global__ void convert_rel(const float* __restrict__ r0, const float* __restrict__ r1) {
    const int h = blockIdx.y, row = blockIdx.x;
    const float* src = h ? r1 : r0;
    __nv_bfloat16* oh = g_relhi[h] + (size_t)row * Dn;
    __nv_bfloat16* ol = g_rello[h] + (size_t)row * Dn;
    for (int c = threadIdx.x; c < Dn; c += 256) {
        float v = (row < NRreal) ? src[(size_t)row * Dn + c] : 0.f;
        __nv_bfloat16 hh = __float2bfloat16(v);
        oh[c] = hh;
        ol[c] = __float2bfloat16(v - __bfloat162float(hh));
    }
}

// ------------------------------- GEMM kernels ------------------------------
__global__ __launch_bounds__(NTH, 2)
void proj_mma(const float* __restrict__ bq0, const float* __restrict__ bk0,
              const float* __restrict__ bq1, const float* __restrict__ bk1) {
    const int z = blockIdx.z;
    const int rowBase = blockIdx.y * BM, colBase = blockIdx.x * BN;
    float* Cs = gemm_stage(g_Xhi + (size_t)rowBase * Dn, g_Xlo + (size_t)rowBase * Dn,
                           g_Wt_hi[z] + (size_t)colBase * Dn,
                           g_Wt_lo[z] + (size_t)colBase * Dn);
    const float* bias = (z==0)?bq0:(z==1)?bk0:(z==2)?bq1:bk1;
    const float alpha = (z & 1) ? 1.0f : 0.03125f;     // q gets 1/sqrt(1024)
    __nv_bfloat16* oh = (z==0)?g_qhi[0]:(z==1)?g_khi[0]:(z==2)?g_qhi[1]:g_khi[1];
    __nv_bfloat16* ol = (z==0)?g_qlo[0]:(z==1)?g_klo[0]:(z==2)?g_qlo[1]:g_klo[1];
    for (int it = threadIdx.x; it < BM * BN; it += NTH) {
        const int row = it >> 7, c = it & 127;
        float v = (Cs[row * LDS_C + c] + bias[colBase + c]) * alpha;
        __nv_bfloat16 h = __float2bfloat16(v);
        size_t o = (size_t)(rowBase + row) * Dn + colBase + c;
        oh[o] = h;
        ol[o] = __float2bfloat16(v - __bfloat162float(h));
    }
}

__global__ __launch_bounds__(NTH, 2)
void qr_mma() {
    const int h = blockIdx.z;
    const int rowBase = blockIdx.y * BM, colBase = blockIdx.x * BN;
    float* Cs = gemm_stage(g_qhi[h] + (size_t)rowBase * Dn,
                           g_qlo[h] + (size_t)rowBase * Dn,
                           g_relhi[h] + (size_t)colBase * Dn,
                           g_rello[h] + (size_t)colBase * Dn);
    for (int it = threadIdx.x; it < BM * BN; it += NTH) {
        const int row = it >> 7, c = it & 127;
        g_qr2[h][(size_t)(rowBase + row) * NRpad + colBase + c] = Cs[row * LDS_C + c];
    }
}

__global__ __launch_bounds__(NTH, 2)
void scores_mma(const int* __restrict__ mask, float* __restrict__ gout) {
    const int z = blockIdx.z, h = z >> 2, b = z & 3;
    const int rowBase = blockIdx.y * BM, colBase = blockIdx.x * BN;
    float* Cs = gemm_stage(g_qhi[h] + ((size_t)b * Tn + rowBase) * Dn,
                           g_qlo[h] + ((size_t)b * Tn + rowBase) * Dn,
                           g_khi[h] + ((size_t)b * Tn + colBase) * Dn,
                           g_klo[h] + ((size_t)b * Tn + colBase) * Dn);
    const float* QR  = g_qr2[h] + (size_t)b * Tn * NRpad;
    const int*   Msk = mask + (size_t)b * Tn * Tn;
    float*       Out = gout + (size_t)h * Bn * Tn * Tn + (size_t)b * Tn * Tn;
    for (int it = threadIdx.x; it < BM * BN; it += NTH) {
        const int row = it >> 7, c = it & 127;
        const int i = rowBase + row, j = colBase + c;
        int d = j - i; d = d < -Rn ? -Rn : (d > Rn ? Rn : d);
        float v = Cs[row * LDS_C + c] + QR[(size_t)i * NRpad + d + Rn];
        Out[(size_t)i * Tn + j] = Msk[(size_t)i * Tn + j] ? v : -1e18f;
    }
}

// --------------------------------- launch ----------------------------------
extern "C" void kernel_launch(void* const* d_in, const int* in_sizes, int n_in,
                              void* d_out, int out_size)
{
    (void)in_sizes; (void)n_in; (void)out_size;
    const float* repre  = (const float*)d_in[0];
    const int*   mask   = (const int*)  d_in[1];
    const float* st_Wq  = (const float*)d_in[2];
    const float* st_bq  = (const float*)d_in[3];
    const float* st_Wk  = (const float*)d_in[4];
    const float* st_bk  = (const float*)d_in[5];
    const float* st_rel = (const float*)d_in[6];
    const float* ed_Wq  = (const float*)d_in[7];
    const float* ed_bq  = (const float*)d_in[8];
    const float* ed_Wk  = (const float*)d_in[9];
    const float* ed_bk  = (const float*)d_in[10];
    const float* ed_rel = (const float*)d_in[11];
    float* out = (float*)d_out;

    static bool attr_set = false;
    if (!attr_set) {
        cudaFuncSetAttribute(proj_mma,   cudaFuncAttributeMaxDynamicSharedMemorySize, SMEM_BYTES);
        cudaFuncSetAttribute(qr_mma,     cudaFuncAttributeMaxDynamicSharedMemorySize, SMEM_BYTES);
        cudaFuncSetAttribute(scores_mma, cudaFuncAttributeMaxDynamicSharedMemorySize, SMEM_BYTES);
        attr_set = true;
    }

    convert_X  <<<Mrows * Dn / 512, 256>>>(repre);
    convert_Wt <<<dim3(32, 32, 4), dim3(32, 8)>>>(st_Wq, st_Wk, ed_Wq, ed_Wk);
    convert_rel<<<dim3(NRpad, 2), 256>>>(st_rel, ed_rel);

    proj_mma  <<<dim3(Dn/BN, Mrows/BM, 4), NTH, SMEM_BYTES>>>(st_bq, st_bk, ed_bq, ed_bk);
    qr_mma    <<<dim3(NRpad/BN, Mrows/BM, 2), NTH, SMEM_BYTES>>>();
    scores_mma<<<dim3(Tn/BN, Tn/BM, 8),    NTH, SMEM_BYTES>>>(mask, out);
}

// round 16
// speedup vs baseline: 1.3663x; 1.0617x over previous
#include <cuda_runtime.h>
#include <cuda_bf16.h>
#include <cstdint>

// ===========================================================================
// SpanClassifier via raw mma.sync bf16 hi/lo 3-pass GEMMs (fp32 accumulate).
// (tcgen05 unavailable: harness PTX target is bare sm_103.)
//   q=(X Wq+bq)/32 ; k=X Wk+bk ; S=q k^T + gather(q rel^T) ; mask -> -1e18
// fp32 operands split x = hi + lo (bf16); one GEMM accumulates
// hi*hi + hi*lo + lo*hi over a 3x-K mainloop (lo*lo dropped, ~2^-16 rel).
// R16: 3 CTAs/SM (launch_bounds(128,3)), 2-stage cp.async ring, collapsed
//      address math (linear offsets), single-buffered fragments, direct
//      register epilogue (no smem C staging).
// ===========================================================================

namespace cfg {
constexpr int Bn=4, Tn=2048, Dn=1024, Rn=64;
constexpr int NRpad=256, NRreal=129;
constexpr int Mrows=Bn*Tn;                    // 8192
constexpr int BM=128, BN=128, BK=64;
constexpr int NTH=128;
constexpr int NCH=3*(Dn/BK);                  // 48 chunks (3 passes x 16)
constexpr int A_BYTES=BM*BK*2;                // 16384 (128B rows, swizzled)
constexpr int STAGE_BYTES=2*A_BYTES;          // 32768
constexpr int SMEM_BYTES=2*STAGE_BYTES+1024;  // 66560 (2-stage ring + align)
}
using namespace cfg;

// ------------------------------- scratch -----------------------------------
__device__ __nv_bfloat16 g_Xhi[Mrows*Dn], g_Xlo[Mrows*Dn];
__device__ __nv_bfloat16 g_Wt_hi[4][Dn*Dn], g_Wt_lo[4][Dn*Dn];   // W^T [n][k]
__device__ __nv_bfloat16 g_relhi[2][NRpad*Dn], g_rello[2][NRpad*Dn];
__device__ __nv_bfloat16 g_qhi[2][Mrows*Dn], g_qlo[2][Mrows*Dn];
__device__ __nv_bfloat16 g_khi[2][Mrows*Dn], g_klo[2][Mrows*Dn];
__device__ float         g_qr2[2][Mrows*NRpad];

// ----------------------------- PTX helpers ---------------------------------
__device__ __forceinline__ uint32_t smem_u32(const void* p){
    uint32_t a;
    asm("{ .reg .u64 t; cvta.to.shared.u64 t, %1; cvt.u32.u64 %0, t; }":"=r"(a):"l"(p));
    return a;
}
#define CP_ASYNC16(d,s) asm volatile("cp.async.cg.shared.global [%0], [%1], 16;"::"r"(d),"l"(s))
#define CP_COMMIT()     asm volatile("cp.async.commit_group;":::"memory")
#define CP_WAIT0()      asm volatile("cp.async.wait_group 0;":::"memory")

#define LDSM_X4(r0,r1,r2,r3,a) \
    asm volatile("ldmatrix.sync.aligned.m8n8.x4.shared.b16 {%0,%1,%2,%3}, [%4];" \
                 : "=r"(r0),"=r"(r1),"=r"(r2),"=r"(r3) : "r"(a))
#define MMA16816(d,a,b0,b1) \
    asm volatile("mma.sync.aligned.m16n8k16.row.col.f32.bf16.bf16.f32 " \
                 "{%0,%1,%2,%3}, {%4,%5,%6,%7}, {%8,%9}, {%0,%1,%2,%3};" \
                 : "+f"((d)[0]),"+f"((d)[1]),"+f"((d)[2]),"+f"((d)[3]) \
                 : "r"((a)[0]),"r"((a)[1]),"r"((a)[2]),"r"((a)[3]), "r"(b0),"r"(b1))

// ---------------------------------------------------------------------------
// Mainloop: acc[4][8][4] += sum over 48 BK=64 chunks of Atile @ Btile^T.
// Swizzle: 128B rows; 16B segment s of row r lives at (s ^ (r&7))*16.
// All cp.async offsets are base + l*const; all ldmatrix addrs (P+t*2048)^x.
// ---------------------------------------------------------------------------
__device__ __forceinline__ void gemm_mainloop(
    float (&acc)[4][8][4],
    const __nv_bfloat16* __restrict__ Ah, const __nv_bfloat16* __restrict__ Al,
    const __nv_bfloat16* __restrict__ Bh, const __nv_bfloat16* __restrict__ Bl)
{
    extern __shared__ char smem_raw[];
    const uint32_t sm0 = (smem_u32(smem_raw) + 1023) & ~1023u;

    const int tid = threadIdx.x;
    const int wid = tid >> 5, lane = tid & 31;
    const int warp_m = wid >> 1, warp_n = wid & 1;    // 2x2 warps, 64x64 tiles
    const int lrow = lane & 15, lhalf = lane >> 4;

    // ldmatrix base offsets (tile t at +t*2048; k-step ks via ^ (ks<<5)).
    const uint32_t swzf = (uint32_t)((lhalf ^ (lrow & 7)) << 4);
    const uint32_t rpA0 = (uint32_t)(warp_m*64 + lrow)*128 + swzf;
    const uint32_t rpB0 = (uint32_t)(warp_n*64 + lrow)*128 + swzf;

    // cp.async base offsets (row block l at +l*2048 smem / +l*16*Dn global).
    const int r0 = tid >> 3;                            // 0..15
    const uint32_t so0 = (uint32_t)r0*128 + (uint32_t)(((tid & 7) ^ (r0 & 7)) << 4);
    const size_t   go0 = (size_t)r0 * Dn + (size_t)(tid & 7) * 8;

    auto load_chunk = [&](int c){
        const uint32_t dA = sm0 + (uint32_t)(c & 1) * STAGE_BYTES;
        const uint32_t dB = dA + A_BYTES;
        const int pass = c >> 4;
        const int kof  = (c & 15) * BK;
        const __nv_bfloat16* A = ((pass == 2) ? Al : Ah) + go0 + kof;
        const __nv_bfloat16* B = ((pass == 1) ? Bl : Bh) + go0 + kof;
        #pragma unroll
        for (int l = 0; l < 8; l++) {
            CP_ASYNC16(dA + so0 + l*2048, A + (size_t)l*16*Dn);
            CP_ASYNC16(dB + so0 + l*2048, B + (size_t)l*16*Dn);
        }
    };

    #pragma unroll
    for (int m = 0; m < 4; m++)
        #pragma unroll
        for (int n = 0; n < 8; n++)
            #pragma unroll
            for (int e = 0; e < 4; e++) acc[m][n][e] = 0.f;

    load_chunk(0); CP_COMMIT();

    for (int i = 0; i < NCH; i++) {
        CP_WAIT0();          // chunk i resident (this warp's copies)
        __syncthreads();     // everyone's chunk i visible; compute(i-1) done
        if (i + 1 < NCH) { load_chunk(i + 1); CP_COMMIT(); }  // flies over compute(i)

        const uint32_t dA = sm0 + (uint32_t)(i & 1) * STAGE_BYTES;
        const uint32_t PA = dA + rpA0;
        const uint32_t PB = dA + A_BYTES + rpB0;
        #pragma unroll
        for (int ks = 0; ks < 4; ks++) {
            uint32_t fa[4][4], fb[4][4];
            const uint32_t x = (uint32_t)(ks << 5);
            #pragma unroll
            for (int t = 0; t < 4; t++) {
                LDSM_X4(fa[t][0],fa[t][1],fa[t][2],fa[t][3], (PA + t*2048) ^ x);
                LDSM_X4(fb[t][0],fb[t][1],fb[t][2],fb[t][3], (PB + t*2048) ^ x);
            }
            // B x4 regs: r0=n[0:8)k[0:8), r1=n[8:16)k[0:8),
            //            r2=n[0:8)k[8:16), r3=n[8:16)k[8:16).
            #pragma unroll
            for (int mt = 0; mt < 4; mt++)
                #pragma unroll
                for (int nt = 0; nt < 4; nt++) {
                    MMA16816(acc[mt][nt*2+0], fa[mt], fb[nt][0], fb[nt][2]);
                    MMA16816(acc[mt][nt*2+1], fa[mt], fb[nt][1], fb[nt][3]);
                }
        }
    }
}

// ------------------------------ conversions --------------------------------
__global__ void convert_X(const float* __restrict__ s) {
    int i = blockIdx.x * 256 + threadIdx.x;              // over float2
    float2 v = reinterpret_cast<const float2*>(s)[i];
    __nv_bfloat16 h0 = __float2bfloat16(v.x), h1 = __float2bfloat16(v.y);
    reinterpret_cast<__nv_bfloat162*>(g_Xhi)[i] = __nv_bfloat162(h0, h1);
    reinterpret_cast<__nv_bfloat162*>(g_Xlo)[i] = __nv_bfloat162(
        __float2bfloat16(v.x - __bfloat162float(h0)),
        __float2bfloat16(v.y - __bfloat162float(h1)));
}

__global__ void convert_Wt(const float* __restrict__ W0, const float* __restrict__ W1,
                           const float* __restrict__ W2, const float* __restrict__ W3) {
    __shared__ float t[32][33];
    const int z = blockIdx.z;
    const float* W = (z==0)?W0:(z==1)?W1:(z==2)?W2:W3;
    const int x0 = blockIdx.x * 32, y0 = blockIdx.y * 32;    // x: n, y: k
    const int tx = threadIdx.x, ty = threadIdx.y;
    #pragma unroll
    for (int i = 0; i < 4; i++)
        t[ty + i*8][tx] = W[(size_t)(y0 + ty + i*8) * Dn + x0 + tx];
    __syncthreads();
    #pragma unroll
    for (int i = 0; i < 4; i++) {
        float v = t[tx][ty + i*8];
        __nv_bfloat16 h = __float2bfloat16(v);
        size_t o = (size_t)(x0 + ty + i*8) * Dn + y0 + tx;
        g_Wt_hi[z][o] = h;
        g_Wt_lo[z][o] = __float2bfloat16(v - __bfloat162float(h));
    }
}

__global__ void convert_rel(const float* __restrict__ r0, const float* __restrict__ r1) {
    const int h = blockIdx.y, row = blockIdx.x;
    const float* src = h ? r1 : r0;
    __nv_bfloat16* oh = g_relhi[h] + (size_t)row * Dn;
    __nv_bfloat16* ol = g_rello[h] + (size_t)row * Dn;
    for (int c = threadIdx.x; c < Dn; c += 256) {
        float v = (row < NRreal) ? src[(size_t)row * Dn + c] : 0.f;
        __nv_bfloat16 hh = __float2bfloat16(v);
        oh[c] = hh;
        ol[c] = __float2bfloat16(v - __bfloat162float(hh));
    }
}

// ------------------------------- GEMM kernels ------------------------------
// Fragment->global mapping: acc[mt][j] elems {0,1} -> row er, {2,3} -> er+8;
// cols = warp_n*64 + (j>>1)*16 + (j&1)*8 + 2*(lane&3) + {0,1}.

__global__ __launch_bounds__(NTH, 3)
void proj_mma(const float* __restrict__ bq0, const float* __restrict__ bk0,
              const float* __restrict__ bq1, const float* __restrict__ bk1) {
    const int z = blockIdx.z;
    const int rowBase = blockIdx.y * BM, colBase = blockIdx.x * BN;
    float acc[4][8][4];
    gemm_mainloop(acc,
        g_Xhi + (size_t)rowBase * Dn, g_Xlo + (size_t)rowBase * Dn,
        g_Wt_hi[z] + (size_t)colBase * Dn, g_Wt_lo[z] + (size_t)colBase * Dn);

    const float* bias = (z==0)?bq0:(z==1)?bk0:(z==2)?bq1:bk1;
    const float alpha = (z & 1) ? 1.0f : 0.03125f;     // q gets 1/sqrt(1024)
    __nv_bfloat16* oh = (z==0)?g_qhi[0]:(z==1)?g_khi[0]:(z==2)?g_qhi[1]:g_khi[1];
    __nv_bfloat16* ol = (z==0)?g_qlo[0]:(z==1)?g_klo[0]:(z==2)?g_qlo[1]:g_klo[1];

    const int lane = threadIdx.x & 31, wid = threadIdx.x >> 5;
    const int warp_m = wid >> 1, warp_n = wid & 1;
    const int er = lane >> 2, ec = (lane & 3) * 2;
    #pragma unroll
    for (int mt = 0; mt < 4; mt++) {
        #pragma unroll
        for (int j = 0; j < 8; j++) {
            const int c0 = colBase + warp_n*64 + (j>>1)*16 + (j&1)*8 + ec;
            const float2 bv = *reinterpret_cast<const float2*>(bias + c0);
            #pragma unroll
            for (int hr = 0; hr < 2; hr++) {
                const int r = rowBase + warp_m*64 + mt*16 + er + hr*8;
                const float v0 = (acc[mt][j][hr*2+0] + bv.x) * alpha;
                const float v1 = (acc[mt][j][hr*2+1] + bv.y) * alpha;
                const __nv_bfloat16 h0 = __float2bfloat16(v0);
                const __nv_bfloat16 h1 = __float2bfloat16(v1);
                const size_t o = (size_t)r * Dn + c0;
                *reinterpret_cast<__nv_bfloat162*>(oh + o) = __nv_bfloat162(h0, h1);
                *reinterpret_cast<__nv_bfloat162*>(ol + o) = __nv_bfloat162(
                    __float2bfloat16(v0 - __bfloat162float(h0)),
                    __float2bfloat16(v1 - __bfloat162float(h1)));
            }
        }
    }
}

__global__ __launch_bounds__(NTH, 3)
void qr_mma() {
    const int h = blockIdx.z;
    const int rowBase = blockIdx.y * BM, colBase = blockIdx.x * BN;
    float acc[4][8][4];
    gemm_mainloop(acc,
        g_qhi[h] + (size_t)rowBase * Dn, g_qlo[h] + (size_t)rowBase * Dn,
        g_relhi[h] + (size_t)colBase * Dn, g_rello[h] + (size_t)colBase * Dn);

    const int lane = threadIdx.x & 31, wid = threadIdx.x >> 5;
    const int warp_m = wid >> 1, warp_n = wid & 1;
    const int er = lane >> 2, ec = (lane & 3) * 2;
    #pragma unroll
    for (int mt = 0; mt < 4; mt++)
        #pragma unroll
        for (int j = 0; j < 8; j++) {
            const int c0 = colBase + warp_n*64 + (j>>1)*16 + (j&1)*8 + ec;
            #pragma unroll
            for (int hr = 0; hr < 2; hr++) {
                const int r = rowBase + warp_m*64 + mt*16 + er + hr*8;
                *reinterpret_cast<float2*>(&g_qr2[h][(size_t)r * NRpad + c0]) =
                    make_float2(acc[mt][j][hr*2+0], acc[mt][j][hr*2+1]);
            }
        }
}

__global__ __launch_bounds__(NTH, 3)
void scores_mma(const int* __restrict__ mask, float* __restrict__ gout) {
    const int z = blockIdx.z, h = z >> 2, b = z & 3;
    const int rowBase = blockIdx.y * BM, colBase = blockIdx.x * BN;
    float acc[4][8][4];
    gemm_mainloop(acc,
        g_qhi[h] + ((size_t)b * Tn + rowBase) * Dn,
        g_qlo[h] + ((size_t)b * Tn + rowBase) * Dn,
        g_khi[h] + ((size_t)b * Tn + colBase) * Dn,
        g_klo[h] + ((size_t)b * Tn + colBase) * Dn);

    const float* QR  = g_qr2[h] + (size_t)b * Tn * NRpad;
    const int*   Msk = mask + (size_t)b * Tn * Tn;
    float*       Out = gout + (size_t)h * Bn * Tn * Tn + (size_t)b * Tn * Tn;

    const int lane = threadIdx.x & 31, wid = threadIdx.x >> 5;
    const int warp_m = wid >> 1, warp_n = wid & 1;
    const int er = lane >> 2, ec = (lane & 3) * 2;
    #pragma unroll
    for (int mt = 0; mt < 4; mt++) {
        #pragma unroll
        for (int hr = 0; hr < 2; hr++) {
            const int i0 = rowBase + warp_m*64 + mt*16 + er + hr*8;
            const float* qr_row = QR + (size_t)i0 * NRpad + Rn;
            #pragma unroll
            for (int j = 0; j < 8; j++) {
                const int j0 = colBase + warp_n*64 + (j>>1)*16 + (j&1)*8 + ec;
                int d0 = j0 - i0;     d0 = d0 < -Rn ? -Rn : (d0 > Rn ? Rn : d0);
                int d1 = j0 + 1 - i0; d1 = d1 < -Rn ? -Rn : (d1 > Rn ? Rn : d1);
                const float v0 = acc[mt][j][hr*2+0] + qr_row[d0];
                const float v1 = acc[mt][j][hr*2+1] + qr_row[d1];
                const int2 mk = *reinterpret_cast<const int2*>(Msk + (size_t)i0 * Tn + j0);
                *reinterpret_cast<float2*>(Out + (size_t)i0 * Tn + j0) =
                    make_float2(mk.x ? v0 : -1e18f, mk.y ? v1 : -1e18f);
            }
        }
    }
}

// --------------------------------- launch ----------------------------------
extern "C" void kernel_launch(void* const* d_in, const int* in_sizes, int n_in,
                              void* d_out, int out_size)
{
    (void)in_sizes; (void)n_in; (void)out_size;
    const float* repre  = (const float*)d_in[0];
    const int*   mask   = (const int*)  d_in[1];
    const float* st_Wq  = (const float*)d_in[2];
    const float* st_bq  = (const float*)d_in[3];
    const float* st_Wk  = (const float*)d_in[4];
    const float* st_bk  = (const float*)d_in[5];
    const float* st_rel = (const float*)d_in[6];
    const float* ed_Wq  = (const float*)d_in[7];
    const float* ed_bq  = (const float*)d_in[8];
    const float* ed_Wk  = (const float*)d_in[9];
    const float* ed_bk  = (const float*)d_in[10];
    const float* ed_rel = (const float*)d_in[11];
    float* out = (float*)d_out;

    static bool attr_set = false;
    if (!attr_set) {
        cudaFuncSetAttribute(proj_mma,   cudaFuncAttributeMaxDynamicSharedMemorySize, SMEM_BYTES);
        cudaFuncSetAttribute(qr_mma,     cudaFuncAttributeMaxDynamicSharedMemorySize, SMEM_BYTES);
        cudaFuncSetAttribute(scores_mma, cudaFuncAttributeMaxDynamicSharedMemorySize, SMEM_BYTES);
        attr_set = true;
    }

    convert_X  <<<Mrows * Dn / 512, 256>>>(repre);
    convert_Wt <<<dim3(32, 32, 4), dim3(32, 8)>>>(st_Wq, st_Wk, ed_Wq, ed_Wk);
    convert_rel<<<dim3(NRpad, 2), 256>>>(st_rel, ed_rel);

    proj_mma  <<<dim3(Dn/BN, Mrows/BM, 4), NTH, SMEM_BYTES>>>(st_bq, st_bk, ed_bq, ed_bk);
    qr_mma    <<<dim3(NRpad/BN, Mrows/BM, 2), NTH, SMEM_BYTES>>>();
    scores_mma<<<dim3(Tn/BN, Tn/BM, 8),    NTH, SMEM_BYTES>>>(mask, out);
}

// round 17
// speedup vs baseline: 1.5409x; 1.1278x over previous
#include <cuda_runtime.h>
#include <cuda_bf16.h>
#include <cstdint>

// ===========================================================================
// SpanClassifier via raw mma.sync bf16 hi/lo 3-pass GEMMs (fp32 accumulate).
// (tcgen05 unavailable: harness PTX target is bare sm_103.)
//   q=(X Wq+bq)/32 ; k=X Wk+bk ; S=q k^T + gather(q rel^T) ; mask -> -1e18
// fp32 operands split x = hi + lo (bf16); one GEMM accumulates
// hi*hi + hi*lo + lo*hi over a 3x-K mainloop (lo*lo dropped, ~2^-16 rel).
// R17: best-of-both recombination:
//   - R15 mainloop: 3-stage cp.async ring, wait_group 1 (one stage of
//     prefetch slack), cross-ks fragment double buffering (tensor 60.8%).
//   - R16 epilogue: direct register->global (no smem C staging).
//   smem = 3 stages only = 99KB -> 2 CTAs/SM; regs ~214 fits 2-CTA budget.
// ===========================================================================

namespace cfg {
constexpr int Bn=4, Tn=2048, Dn=1024, Rn=64;
constexpr int NRpad=256, NRreal=129;
constexpr int Mrows=Bn*Tn;                    // 8192
constexpr int BM=128, BN=128, BK=64;
constexpr int NTH=128;
constexpr int NCH=3*(Dn/BK);                  // 48 chunks (3 passes x 16)
constexpr int STAGES=3;
constexpr int A_BYTES=BM*BK*2;                // 16384 (128B rows, swizzled)
constexpr int STAGE_BYTES=2*A_BYTES;          // 32768
constexpr int SMEM_BYTES=STAGES*STAGE_BYTES+1024; // 99328
}
using namespace cfg;

// ------------------------------- scratch -----------------------------------
__device__ __nv_bfloat16 g_Xhi[Mrows*Dn], g_Xlo[Mrows*Dn];
__device__ __nv_bfloat16 g_Wt_hi[4][Dn*Dn], g_Wt_lo[4][Dn*Dn];   // W^T [n][k]
__device__ __nv_bfloat16 g_relhi[2][NRpad*Dn], g_rello[2][NRpad*Dn];
__device__ __nv_bfloat16 g_qhi[2][Mrows*Dn], g_qlo[2][Mrows*Dn];
__device__ __nv_bfloat16 g_khi[2][Mrows*Dn], g_klo[2][Mrows*Dn];
__device__ float         g_qr2[2][Mrows*NRpad];

// ----------------------------- PTX helpers ---------------------------------
__device__ __forceinline__ uint32_t smem_u32(const void* p){
    uint32_t a;
    asm("{ .reg .u64 t; cvta.to.shared.u64 t, %1; cvt.u32.u64 %0, t; }":"=r"(a):"l"(p));
    return a;
}
#define CP_ASYNC16(d,s) asm volatile("cp.async.cg.shared.global [%0], [%1], 16;"::"r"(d),"l"(s))
#define CP_COMMIT()     asm volatile("cp.async.commit_group;":::"memory")
#define CP_WAIT1()      asm volatile("cp.async.wait_group 1;":::"memory")
#define CP_WAIT0()      asm volatile("cp.async.wait_group 0;":::"memory")

#define LDSM_X4(r0,r1,r2,r3,a) \
    asm volatile("ldmatrix.sync.aligned.m8n8.x4.shared.b16 {%0,%1,%2,%3}, [%4];" \
                 : "=r"(r0),"=r"(r1),"=r"(r2),"=r"(r3) : "r"(a))
#define MMA16816(d,a,b0,b1) \
    asm volatile("mma.sync.aligned.m16n8k16.row.col.f32.bf16.bf16.f32 " \
                 "{%0,%1,%2,%3}, {%4,%5,%6,%7}, {%8,%9}, {%0,%1,%2,%3};" \
                 : "+f"((d)[0]),"+f"((d)[1]),"+f"((d)[2]),"+f"((d)[3]) \
                 : "r"((a)[0]),"r"((a)[1]),"r"((a)[2]),"r"((a)[3]), "r"(b0),"r"(b1))

// ---------------------------------------------------------------------------
// Mainloop: acc[4][8][4] += sum over 48 BK=64 chunks of Atile @ Btile^T.
// Swizzle: 128B rows; 16B segment s of row r lives at (s ^ (r&7))*16.
// 3-stage ring, wait_group 1, cross-ks fragment double buffering.
// ---------------------------------------------------------------------------
__device__ __forceinline__ void gemm_mainloop(
    float (&acc)[4][8][4],
    const __nv_bfloat16* __restrict__ Ah, const __nv_bfloat16* __restrict__ Al,
    const __nv_bfloat16* __restrict__ Bh, const __nv_bfloat16* __restrict__ Bl)
{
    extern __shared__ char smem_raw[];
    const uint32_t sm0 = (smem_u32(smem_raw) + 1023) & ~1023u;

    const int tid = threadIdx.x;
    const int wid = tid >> 5, lane = tid & 31;
    const int warp_m = wid >> 1, warp_n = wid & 1;    // 2x2 warps, 64x64 tiles
    const int lrow = lane & 15, lhalf = lane >> 4;

    // ldmatrix base offsets (tile t at +t*2048; k-step ks via ^ (ks<<5)).
    const uint32_t swzf = (uint32_t)((lhalf ^ (lrow & 7)) << 4);
    const uint32_t rpA0 = (uint32_t)(warp_m*64 + lrow)*128 + swzf;
    const uint32_t rpB0 = (uint32_t)(warp_n*64 + lrow)*128 + swzf;

    // cp.async base offsets (row block l at +l*2048 smem / +l*16*Dn global).
    const int r0 = tid >> 3;                            // 0..15
    const uint32_t so0 = (uint32_t)r0*128 + (uint32_t)(((tid & 7) ^ (r0 & 7)) << 4);
    const size_t   go0 = (size_t)r0 * Dn + (size_t)(tid & 7) * 8;

    auto load_chunk = [&](int c){
        const uint32_t dA = sm0 + (uint32_t)(c % STAGES) * STAGE_BYTES;
        const uint32_t dB = dA + A_BYTES;
        const int pass = c >> 4;
        const int kof  = (c & 15) * BK;
        const __nv_bfloat16* A = ((pass == 2) ? Al : Ah) + go0 + kof;
        const __nv_bfloat16* B = ((pass == 1) ? Bl : Bh) + go0 + kof;
        #pragma unroll
        for (int l = 0; l < 8; l++) {
            CP_ASYNC16(dA + so0 + l*2048, A + (size_t)l*16*Dn);
            CP_ASYNC16(dB + so0 + l*2048, B + (size_t)l*16*Dn);
        }
    };

    #pragma unroll
    for (int m = 0; m < 4; m++)
        #pragma unroll
        for (int n = 0; n < 8; n++)
            #pragma unroll
            for (int e = 0; e < 4; e++) acc[m][n][e] = 0.f;

    load_chunk(0); CP_COMMIT();
    load_chunk(1); CP_COMMIT();

    uint32_t fa[2][4][4], fb[2][4][4];

    for (int i = 0; i < NCH; i++) {
        CP_WAIT1();          // chunk i resident (i+1 may be in flight)
        __syncthreads();     // all warps done with compute(i-1)
        if (i + 2 < NCH) load_chunk(i + 2);
        CP_COMMIT();         // empty tail groups keep counting uniform

        const uint32_t dA = sm0 + (uint32_t)(i % STAGES) * STAGE_BYTES;
        const uint32_t PA = dA + rpA0;
        const uint32_t PB = dA + A_BYTES + rpB0;

        // Fetch ks=0 fragments.
        #pragma unroll
        for (int t = 0; t < 4; t++) {
            LDSM_X4(fa[0][t][0],fa[0][t][1],fa[0][t][2],fa[0][t][3], PA + t*2048);
            LDSM_X4(fb[0][t][0],fb[0][t][1],fb[0][t][2],fb[0][t][3], PB + t*2048);
        }
        #pragma unroll
        for (int ks = 0; ks < 4; ks++) {
            const int cur = ks & 1, nxt = cur ^ 1;
            if (ks < 3) {
                const uint32_t x = (uint32_t)((ks + 1) << 5);
                #pragma unroll
                for (int t = 0; t < 4; t++) {
                    LDSM_X4(fa[nxt][t][0],fa[nxt][t][1],fa[nxt][t][2],fa[nxt][t][3],
                            (PA + t*2048) ^ x);
                    LDSM_X4(fb[nxt][t][0],fb[nxt][t][1],fb[nxt][t][2],fb[nxt][t][3],
                            (PB + t*2048) ^ x);
                }
            }
            // B x4 regs: r0=n[0:8)k[0:8), r1=n[8:16)k[0:8),
            //            r2=n[0:8)k[8:16), r3=n[8:16)k[8:16).
            #pragma unroll
            for (int mt = 0; mt < 4; mt++)
                #pragma unroll
                for (int nt = 0; nt < 4; nt++) {
                    MMA16816(acc[mt][nt*2+0], fa[cur][mt], fb[cur][nt][0], fb[cur][nt][2]);
                    MMA16816(acc[mt][nt*2+1], fa[cur][mt], fb[cur][nt][1], fb[cur][nt][3]);
                }
        }
    }
}

// ------------------------------ conversions --------------------------------
__global__ void convert_X(const float* __restrict__ s) {
    int i = blockIdx.x * 256 + threadIdx.x;              // over float2
    float2 v = reinterpret_cast<const float2*>(s)[i];
    __nv_bfloat16 h0 = __float2bfloat16(v.x), h1 = __float2bfloat16(v.y);
    reinterpret_cast<__nv_bfloat162*>(g_Xhi)[i] = __nv_bfloat162(h0, h1);
    reinterpret_cast<__nv_bfloat162*>(g_Xlo)[i] = __nv_bfloat162(
        __float2bfloat16(v.x - __bfloat162float(h0)),
        __float2bfloat16(v.y - __bfloat162float(h1)));
}

__global__ void convert_Wt(const float* __restrict__ W0, const float* __restrict__ W1,
                           const float* __restrict__ W2, const float* __restrict__ W3) {
    __shared__ float t[32][33];
    const int z = blockIdx.z;
    const float* W = (z==0)?W0:(z==1)?W1:(z==2)?W2:W3;
    const int x0 = blockIdx.x * 32, y0 = blockIdx.y * 32;    // x: n, y: k
    const int tx = threadIdx.x, ty = threadIdx.y;
    #pragma unroll
    for (int i = 0; i < 4; i++)
        t[ty + i*8][tx] = W[(size_t)(y0 + ty + i*8) * Dn + x0 + tx];
    __syncthreads();
    #pragma unroll
    for (int i = 0; i < 4; i++) {
        float v = t[tx][ty + i*8];
        __nv_bfloat16 h = __float2bfloat16(v);
        size_t o = (size_t)(x0 + ty + i*8) * Dn + y0 + tx;
        g_Wt_hi[z][o] = h;
        g_Wt_lo[z][o] = __float2bfloat16(v - __bfloat162float(h));
    }
}

__global__ void convert_rel(const float* __restrict__ r0, const float* __restrict__ r1) {
    const int h = blockIdx.y, row = blockIdx.x;
    const float* src = h ? r1 : r0;
    __nv_bfloat16* oh = g_relhi[h] + (size_t)row * Dn;
    __nv_bfloat16* ol = g_rello[h] + (size_t)row * Dn;
    for (int c = threadIdx.x; c < Dn; c += 256) {
        float v = (row < NRreal) ? src[(size_t)row * Dn + c] : 0.f;
        __nv_bfloat16 hh = __float2bfloat16(v);
        oh[c] = hh;
        ol[c] = __float2bfloat16(v - __bfloat162float(hh));
    }
}

// ------------------------------- GEMM kernels ------------------------------
// Fragment->global mapping: acc[mt][j] elems {0,1} -> row er, {2,3} -> er+8;
// cols = warp_n*64 + (j>>1)*16 + (j&1)*8 + 2*(lane&3) + {0,1}.

__global__ __launch_bounds__(NTH, 2)
void proj_mma(const float* __restrict__ bq0, const float* __restrict__ bk0,
              const float* __restrict__ bq1, const float* __restrict__ bk1) {
    const int z = blockIdx.z;
    const int rowBase = blockIdx.y * BM, colBase = blockIdx.x * BN;
    float acc[4][8][4];
    gemm_mainloop(acc,
        g_Xhi + (size_t)rowBase * Dn, g_Xlo + (size_t)rowBase * Dn,
        g_Wt_hi[z] + (size_t)colBase * Dn, g_Wt_lo[z] + (size_t)colBase * Dn);

    const float* bias = (z==0)?bq0:(z==1)?bk0:(z==2)?bq1:bk1;
    const float alpha = (z & 1) ? 1.0f : 0.03125f;     // q gets 1/sqrt(1024)
    __nv_bfloat16* oh = (z==0)?g_qhi[0]:(z==1)?g_khi[0]:(z==2)?g_qhi[1]:g_khi[1];
    __nv_bfloat16* ol = (z==0)?g_qlo[0]:(z==1)?g_klo[0]:(z==2)?g_qlo[1]:g_klo[1];

    const int lane = threadIdx.x & 31, wid = threadIdx.x >> 5;
    const int warp_m = wid >> 1, warp_n = wid & 1;
    const int er = lane >> 2, ec = (lane & 3) * 2;
    #pragma unroll
    for (int mt = 0; mt < 4; mt++) {
        #pragma unroll
        for (int j = 0; j < 8; j++) {
            const int c0 = colBase + warp_n*64 + (j>>1)*16 + (j&1)*8 + ec;
            const float2 bv = *reinterpret_cast<const float2*>(bias + c0);
            #pragma unroll
            for (int hr = 0; hr < 2; hr++) {
                const int r = rowBase + warp_m*64 + mt*16 + er + hr*8;
                const float v0 = (acc[mt][j][hr*2+0] + bv.x) * alpha;
                const float v1 = (acc[mt][j][hr*2+1] + bv.y) * alpha;
                const __nv_bfloat16 h0 = __float2bfloat16(v0);
                const __nv_bfloat16 h1 = __float2bfloat16(v1);
                const size_t o = (size_t)r * Dn + c0;
                *reinterpret_cast<__nv_bfloat162*>(oh + o) = __nv_bfloat162(h0, h1);
                *reinterpret_cast<__nv_bfloat162*>(ol + o) = __nv_bfloat162(
                    __float2bfloat16(v0 - __bfloat162float(h0)),
                    __float2bfloat16(v1 - __bfloat162float(h1)));
            }
        }
    }
}

__global__ __launch_bounds__(NTH, 2)
void qr_mma() {
    const int h = blockIdx.z;
    const int rowBase = blockIdx.y * BM, colBase = blockIdx.x * BN;
    float acc[4][8][4];
    gemm_mainloop(acc,
        g_qhi[h] + (size_t)rowBase * Dn, g_qlo[h] + (size_t)rowBase * Dn,
        g_relhi[h] + (size_t)colBase * Dn, g_rello[h] + (size_t)colBase * Dn);

    const int lane = threadIdx.x & 31, wid = threadIdx.x >> 5;
    const int warp_m = wid >> 1, warp_n = wid & 1;
    const int er = lane >> 2, ec = (lane & 3) * 2;
    #pragma unroll
    for (int mt = 0; mt < 4; mt++)
        #pragma unroll
        for (int j = 0; j < 8; j++) {
            const int c0 = colBase + warp_n*64 + (j>>1)*16 + (j&1)*8 + ec;
            #pragma unroll
            for (int hr = 0; hr < 2; hr++) {
                const int r = rowBase + warp_m*64 + mt*16 + er + hr*8;
                *reinterpret_cast<float2*>(&g_qr2[h][(size_t)r * NRpad + c0]) =
                    make_float2(acc[mt][j][hr*2+0], acc[mt][j][hr*2+1]);
            }
        }
}

__global__ __launch_bounds__(NTH, 2)
void scores_mma(const int* __restrict__ mask, float* __restrict__ gout) {
    const int z = blockIdx.z, h = z >> 2, b = z & 3;
    const int rowBase = blockIdx.y * BM, colBase = blockIdx.x * BN;
    float acc[4][8][4];
    gemm_mainloop(acc,
        g_qhi[h] + ((size_t)b * Tn + rowBase) * Dn,
        g_qlo[h] + ((size_t)b * Tn + rowBase) * Dn,
        g_khi[h] + ((size_t)b * Tn + colBase) * Dn,
        g_klo[h] + ((size_t)b * Tn + colBase) * Dn);

    const float* QR  = g_qr2[h] + (size_t)b * Tn * NRpad;
    const int*   Msk = mask + (size_t)b * Tn * Tn;
    float*       Out = gout + (size_t)h * Bn * Tn * Tn + (size_t)b * Tn * Tn;

    const int lane = threadIdx.x & 31, wid = threadIdx.x >> 5;
    const int warp_m = wid >> 1, warp_n = wid & 1;
    const int er = lane >> 2, ec = (lane & 3) * 2;
    #pragma unroll
    for (int mt = 0; mt < 4; mt++) {
        #pragma unroll
        for (int hr = 0; hr < 2; hr++) {
            const int i0 = rowBase + warp_m*64 + mt*16 + er + hr*8;
            const float* qr_row = QR + (size_t)i0 * NRpad + Rn;
            #pragma unroll
            for (int j = 0; j < 8; j++) {
                const int j0 = colBase + warp_n*64 + (j>>1)*16 + (j&1)*8 + ec;
                int d0 = j0 - i0;     d0 = d0 < -Rn ? -Rn : (d0 > Rn ? Rn : d0);
                int d1 = j0 + 1 - i0; d1 = d1 < -Rn ? -Rn : (d1 > Rn ? Rn : d1);
                const float v0 = acc[mt][j][hr*2+0] + qr_row[d0];
                const float v1 = acc[mt][j][hr*2+1] + qr_row[d1];
                const int2 mk = *reinterpret_cast<const int2*>(Msk + (size_t)i0 * Tn + j0);
                *reinterpret_cast<float2*>(Out + (size_t)i0 * Tn + j0) =
                    make_float2(mk.x ? v0 : -1e18f, mk.y ? v1 : -1e18f);
            }
        }
    }
}

// --------------------------------- launch ----------------------------------
extern "C" void kernel_launch(void* const* d_in, const int* in_sizes, int n_in,
                              void* d_out, int out_size)
{
    (void)in_sizes; (void)n_in; (void)out_size;
    const float* repre  = (const float*)d_in[0];
    const int*   mask   = (const int*)  d_in[1];
    const float* st_Wq  = (const float*)d_in[2];
    const float* st_bq  = (const float*)d_in[3];
    const float* st_Wk  = (const float*)d_in[4];
    const float* st_bk  = (const float*)d_in[5];
    const float* st_rel = (const float*)d_in[6];
    const float* ed_Wq  = (const float*)d_in[7];
    const float* ed_bq  = (const float*)d_in[8];
    const float* ed_Wk  = (const float*)d_in[9];
    const float* ed_bk  = (const float*)d_in[10];
    const float* ed_rel = (const float*)d_in[11];
    float* out = (float*)d_out;

    static bool attr_set = false;
    if (!attr_set) {
        cudaFuncSetAttribute(proj_mma,   cudaFuncAttributeMaxDynamicSharedMemorySize, SMEM_BYTES);
        cudaFuncSetAttribute(qr_mma,     cudaFuncAttributeMaxDynamicSharedMemorySize, SMEM_BYTES);
        cudaFuncSetAttribute(scores_mma, cudaFuncAttributeMaxDynamicSharedMemorySize, SMEM_BYTES);
        attr_set = true;
    }

    convert_X  <<<Mrows * Dn / 512, 256>>>(repre);
    convert_Wt <<<dim3(32, 32, 4), dim3(32, 8)>>>(st_Wq, st_Wk, ed_Wq, ed_Wk);
    convert_rel<<<dim3(NRpad, 2), 256>>>(st_rel, ed_rel);

    proj_mma  <<<dim3(Dn/BN, Mrows/BM, 4), NTH, SMEM_BYTES>>>(st_bq, st_bk, ed_bq, ed_bk);
    qr_mma    <<<dim3(NRpad/BN, Mrows/BM, 2), NTH, SMEM_BYTES>>>();
    scores_mma<<<dim3(Tn/BN, Tn/BM, 8),    NTH, SMEM_BYTES>>>(mask, out);
}